// round 12
// baseline (speedup 1.0000x reference)
#include <cuda_runtime.h>
#include <cuda_bf16.h>

#define N_NODES 50000
#define E_EDGES 800000
#define H_DIM   64
#define GAMMA   0.2f

#define SCAN_CHUNK 1024
#define SCAN_NBLK  ((N_NODES + SCAN_CHUNK - 1) / SCAN_CHUNK)   // 49
#define E_QUARTER  (E_EDGES / 4)                               // 200000, exact

// ---------------- device scratch (static, allocation-free) ----------------
__device__ float    g_vsrc[H_DIM];
__device__ float    g_vdst[H_DIM];
__device__ float    g_s0[N_NODES];
__device__ float    g_d0[N_NODES];
__device__ float    g_s1[N_NODES];
__device__ float    g_d1[N_NODES];
__device__ unsigned g_cnt[N_NODES];
__device__ unsigned g_rowptr[N_NODES + 1];
__device__ unsigned g_cursor[N_NODES];
__device__ unsigned g_blksum[SCAN_NBLK];
__device__ int      g_srcs[E_EDGES];      // src id, grouped by dst (CSR)
__device__ float    g_ex[E_EDGES];        // last-layer exp(e), CSR order
__device__ float    g_dinv[N_NODES];      // last-layer 1/denom
__device__ float    g_h[N_NODES * H_DIM];
__device__ float    g_sumA;
__device__ float    g_sumB;
__device__ unsigned g_done;               // last-block ticket for fused finalize

// ---------------- kernels ----------------

// branch B: v_src = W^T a_src, v_dst = W^T a_dst; zero loss accumulators.
__global__ void k_prep(const float* __restrict__ W, const float* __restrict__ attn) {
    int t = threadIdx.x;  // 128 threads
    if (t == 0) { g_sumA = 0.f; g_sumB = 0.f; g_done = 0u; }
    if (t < H_DIM) {
        float acc = 0.f;
        #pragma unroll 8
        for (int r = 0; r < H_DIM; r++) acc += attn[r] * W[r * H_DIM + t];
        g_vsrc[t] = acc;
    } else {
        int c = t - H_DIM;
        float acc = 0.f;
        #pragma unroll 8
        for (int r = 0; r < H_DIM; r++) acc += attn[H_DIM + r] * W[r * H_DIM + c];
        g_vdst[c] = acc;
    }
}

// branch B: s = emb.v_src, d = emb.v_dst (8 threads per node)
__global__ void k_node_scores(const float* __restrict__ h) {
    int gid  = blockIdx.x * blockDim.x + threadIdx.x;
    int node = gid >> 3;
    int part = gid & 7;
    if (node >= N_NODES) return;   // whole-warp aligned exits (N*8 % 32 == 0)

    const float4* hp = (const float4*)(h + (size_t)node * H_DIM);
    const float4* vs = (const float4*)g_vsrc;
    const float4* vd = (const float4*)g_vdst;
    float4 a = hp[part * 2], b = hp[part * 2 + 1];
    float4 v0 = vs[part * 2], v1 = vs[part * 2 + 1];
    float4 w0 = vd[part * 2], w1 = vd[part * 2 + 1];

    float s = a.x * v0.x + a.y * v0.y + a.z * v0.z + a.w * v0.w
            + b.x * v1.x + b.y * v1.y + b.z * v1.z + b.w * v1.w;
    float d = a.x * w0.x + a.y * w0.y + a.z * w0.z + a.w * w0.w
            + b.x * w1.x + b.y * w1.y + b.z * w1.z + b.w * w1.w;

    #pragma unroll
    for (int off = 4; off; off >>= 1) {
        s += __shfl_xor_sync(0xffffffffu, s, off);
        d += __shfl_xor_sync(0xffffffffu, d, off);
    }
    if (part == 0) { g_s0[node] = s; g_d0[node] = d; }
}

// branch A: histogram dst (x4 per thread: RED has no return -> safe to batch).
__global__ void k_hist(const int* __restrict__ dst) {
    int i = blockIdx.x * blockDim.x + threadIdx.x;
    if (i < E_QUARTER) {
        int4 d = ((const int4*)dst)[i];
        atomicAdd(&g_cnt[d.x], 1u);
        atomicAdd(&g_cnt[d.y], 1u);
        atomicAdd(&g_cnt[d.z], 1u);
        atomicAdd(&g_cnt[d.w], 1u);
    }
}

// per-block exclusive scan of g_cnt -> g_rowptr (block-local), totals -> g_blksum
__global__ void k_scan1() {
    __shared__ unsigned warp_sums[32];
    int t = threadIdx.x, lane = t & 31, wid = t >> 5;
    int idx = blockIdx.x * SCAN_CHUNK + t;

    unsigned orig = (idx < N_NODES) ? g_cnt[idx] : 0u;
    unsigned v = orig;
    #pragma unroll
    for (int o = 1; o < 32; o <<= 1) {
        unsigned u = __shfl_up_sync(0xffffffffu, v, o);
        if (lane >= o) v += u;
    }
    if (lane == 31) warp_sums[wid] = v;
    __syncthreads();
    if (wid == 0) {
        unsigned w = warp_sums[lane];
        #pragma unroll
        for (int o = 1; o < 32; o <<= 1) {
            unsigned u = __shfl_up_sync(0xffffffffu, w, o);
            if (lane >= o) w += u;
        }
        warp_sums[lane] = w;
    }
    __syncthreads();
    unsigned pre = (wid > 0) ? warp_sums[wid - 1] : 0u;
    if (idx < N_NODES) g_rowptr[idx] = pre + v - orig;   // block-local exclusive
    if (t == SCAN_CHUNK - 1) g_blksum[blockIdx.x] = warp_sums[31];
}

// fused scan2+3: each 256-thread block covers nodes inside ONE scan chunk.
__global__ void k_scan23() {
    __shared__ unsigned s_off;
    int chunk = (blockIdx.x * 256) / SCAN_CHUNK;

    if (threadIdx.x < 32) {                 // warp 0: offset for this block
        unsigned v = 0;
        for (int k = threadIdx.x; k < chunk; k += 32) v += g_blksum[k];
        #pragma unroll
        for (int o = 16; o; o >>= 1) v += __shfl_xor_sync(0xffffffffu, v, o);
        if (threadIdx.x == 0) s_off = v;
    } else if (blockIdx.x == 0 && threadIdx.x < 64) {   // warp 1 of block 0: total
        int lane = threadIdx.x - 32;
        unsigned v = 0;
        for (int k = lane; k < SCAN_NBLK; k += 32) v += g_blksum[k];
        #pragma unroll
        for (int o = 16; o; o >>= 1) v += __shfl_xor_sync(0xffffffffu, v, o);
        if (lane == 0) g_rowptr[N_NODES] = v;
    }
    __syncthreads();
    int i = blockIdx.x * 256 + threadIdx.x;
    if (i < N_NODES) {
        unsigned r = g_rowptr[i] + s_off;
        g_rowptr[i] = r;
        g_cursor[i] = r;
    }
}

// branch A: scatter edges into CSR (one edge/thread — batching returning atomics
// measured slower in R8).
__global__ void k_scatter(const int* __restrict__ src, const int* __restrict__ dst) {
    int i = blockIdx.x * blockDim.x + threadIdx.x;
    if (i >= E_EDGES) return;
    unsigned pos = atomicAdd(&g_cursor[dst[i]], 1u);
    g_srcs[pos] = src[i];
}

// fused per-node layer, single pass (softmax shift-invariance: no segment max).
// 16 threads/node; edge loop manually unrolled x4 for MLP.
template <int FINAL, int WSCORES>
__global__ void k_layer(const float* __restrict__ h_in,
                        const float* __restrict__ emb,
                        float* __restrict__ h_out,
                        const float* __restrict__ s_in,
                        const float* __restrict__ d_in) {
    int gid  = blockIdx.x * blockDim.x + threadIdx.x;   // exact grid: N*16
    int node = gid >> 4;
    int part = gid & 15;

    unsigned beg = g_rowptr[node], end = g_rowptr[node + 1];
    float dloc = d_in[node];

    float4 acc = make_float4(0.f, 0.f, 0.f, 0.f);
    float den = 0.f;
    unsigned j = beg;
    for (; j + 4 <= end; j += 4) {
        int s0 = g_srcs[j], s1 = g_srcs[j + 1], s2 = g_srcs[j + 2], s3 = g_srcs[j + 3];
        float e0 = s_in[s0] + dloc, e1 = s_in[s1] + dloc,
              e2 = s_in[s2] + dloc, e3 = s_in[s3] + dloc;
        e0 = e0 > 0.f ? e0 : GAMMA * e0;  e1 = e1 > 0.f ? e1 : GAMMA * e1;
        e2 = e2 > 0.f ? e2 : GAMMA * e2;  e3 = e3 > 0.f ? e3 : GAMMA * e3;
        float x0 = __expf(e0), x1 = __expf(e1), x2 = __expf(e2), x3 = __expf(e3);
        float4 h0 = *(const float4*)(h_in + (size_t)s0 * H_DIM + part * 4);
        float4 h1 = *(const float4*)(h_in + (size_t)s1 * H_DIM + part * 4);
        float4 h2 = *(const float4*)(h_in + (size_t)s2 * H_DIM + part * 4);
        float4 h3 = *(const float4*)(h_in + (size_t)s3 * H_DIM + part * 4);
        den += (x0 + x1) + (x2 + x3);
        acc.x += x0 * h0.x + x1 * h1.x + x2 * h2.x + x3 * h3.x;
        acc.y += x0 * h0.y + x1 * h1.y + x2 * h2.y + x3 * h3.y;
        acc.z += x0 * h0.z + x1 * h1.z + x2 * h2.z + x3 * h3.z;
        acc.w += x0 * h0.w + x1 * h1.w + x2 * h2.w + x3 * h3.w;
        if (FINAL && part == 0) {
            g_ex[j] = x0; g_ex[j + 1] = x1; g_ex[j + 2] = x2; g_ex[j + 3] = x3;
        }
    }
    for (; j < end; j++) {
        int sj = g_srcs[j];
        float e = s_in[sj] + dloc;
        e = e > 0.f ? e : GAMMA * e;
        float ex = __expf(e);
        den += ex;
        float4 hv = *(const float4*)(h_in + (size_t)sj * H_DIM + part * 4);
        acc.x += ex * hv.x; acc.y += ex * hv.y;
        acc.z += ex * hv.z; acc.w += ex * hv.w;
        if (FINAL && part == 0) g_ex[j] = ex;
    }
    float inv = 1.f / fmaxf(den, 1e-16f);
    float4 eb = *(const float4*)(emb + (size_t)node * H_DIM + part * 4);
    float4 hv = make_float4(0.5f * (eb.x + acc.x * inv), 0.5f * (eb.y + acc.y * inv),
                            0.5f * (eb.z + acc.z * inv), 0.5f * (eb.w + acc.w * inv));
    *(float4*)(h_out + (size_t)node * H_DIM + part * 4) = hv;

    // ----- post-loop: all 32 lanes reconverged; full-mask shuffles safe -----
    if (WSCORES) {
        float4 v0 = ((const float4*)g_vsrc)[part];
        float4 w0 = ((const float4*)g_vdst)[part];
        float sp = hv.x * v0.x + hv.y * v0.y + hv.z * v0.z + hv.w * v0.w;
        float dp = hv.x * w0.x + hv.y * w0.y + hv.z * w0.z + hv.w * w0.w;
        #pragma unroll
        for (int off = 8; off; off >>= 1) {
            sp += __shfl_xor_sync(0xffffffffu, sp, off);
            dp += __shfl_xor_sync(0xffffffffu, dp, off);
        }
        if (part == 0) { g_s1[node] = sp; g_d1[node] = dp; }
    }

    if (FINAL) {
        if (part == 0) g_dinv[node] = inv;
        float dx = hv.x - eb.x, dy = hv.y - eb.y, dz = hv.z - eb.z, dw = hv.w - eb.w;
        float sq = dx * dx + dy * dy + dz * dz + dw * dw;
        #pragma unroll
        for (int off = 16; off; off >>= 1) sq += __shfl_xor_sync(0xffffffffu, sq, off);
        __shared__ float sm[8];
        if ((threadIdx.x & 31) == 0) sm[threadIdx.x >> 5] = sq;
        __syncthreads();
        if (threadIdx.x < 8) {
            float v = sm[threadIdx.x];
            #pragma unroll
            for (int o = 4; o; o >>= 1) v += __shfl_xor_sync(0xffu, v, o);
            if (threadIdx.x == 0) atomicAdd(&g_sumA, v);
        }
    }
}

// loss_b, lane-per-part (coalesced), unrolled x2; finalize fused via last-block ticket.
__global__ void k_loss(const float* __restrict__ h, float* __restrict__ out) {
    int gid  = blockIdx.x * blockDim.x + threadIdx.x;   // exact grid: N*16
    int node = gid >> 4;
    int part = gid & 15;
    unsigned gmask = 0xFFFFu << (threadIdx.x & 16);

    unsigned beg = g_rowptr[node], end = g_rowptr[node + 1];
    float4 hd = *(const float4*)(h + (size_t)node * H_DIM + part * 4);
    float dinv = g_dinv[node];

    float sum = 0.f;
    unsigned j = beg;
    for (; j + 2 <= end; j += 2) {
        int s0 = g_srcs[j], s1 = g_srcs[j + 1];
        float4 a0 = *(const float4*)(h + (size_t)s0 * H_DIM + part * 4);
        float4 a1 = *(const float4*)(h + (size_t)s1 * H_DIM + part * 4);
        float q0 = (hd.x - a0.x) * (hd.x - a0.x) + (hd.y - a0.y) * (hd.y - a0.y)
                 + (hd.z - a0.z) * (hd.z - a0.z) + (hd.w - a0.w) * (hd.w - a0.w);
        float q1 = (hd.x - a1.x) * (hd.x - a1.x) + (hd.y - a1.y) * (hd.y - a1.y)
                 + (hd.z - a1.z) * (hd.z - a1.z) + (hd.w - a1.w) * (hd.w - a1.w);
        #pragma unroll
        for (int off = 8; off; off >>= 1) {
            q0 += __shfl_xor_sync(gmask, q0, off);
            q1 += __shfl_xor_sync(gmask, q1, off);
        }
        sum += g_ex[j] * sqrtf(q0 + 1e-12f) + g_ex[j + 1] * sqrtf(q1 + 1e-12f);
    }
    if (j < end) {
        int sj = g_srcs[j];
        float4 a = *(const float4*)(h + (size_t)sj * H_DIM + part * 4);
        float q = (hd.x - a.x) * (hd.x - a.x) + (hd.y - a.y) * (hd.y - a.y)
                + (hd.z - a.z) * (hd.z - a.z) + (hd.w - a.w) * (hd.w - a.w);
        #pragma unroll
        for (int off = 8; off; off >>= 1) q += __shfl_xor_sync(gmask, q, off);
        sum += g_ex[j] * sqrtf(q + 1e-12f);
    }
    sum = (part == 0) ? sum * dinv : 0.f;   // one copy per node
    #pragma unroll
    for (int off = 16; off; off >>= 1) sum += __shfl_xor_sync(0xffffffffu, sum, off);
    __shared__ float sm[8];
    if ((threadIdx.x & 31) == 0) sm[threadIdx.x >> 5] = sum;
    __syncthreads();
    if (threadIdx.x < 8) {
        float v = sm[threadIdx.x];
        #pragma unroll
        for (int o = 4; o; o >>= 1) v += __shfl_xor_sync(0xffu, v, o);
        if (threadIdx.x == 0) {
            atomicAdd(&g_sumB, v);
            __threadfence();
            unsigned ticket = atomicAdd(&g_done, 1u);
            if (ticket == gridDim.x - 1) {           // last block: finalize loss
                float a = *(volatile float*)&g_sumA;
                float b = *(volatile float*)&g_sumB;
                out[N_NODES * H_DIM] = 0.5f * (a + b) / (float)N_NODES;
            }
        }
    }
}

// ---------------- launch ----------------
extern "C" void kernel_launch(void* const* d_in, const int* in_sizes, int n_in,
                              void* d_out, int out_size) {
    const float* emb  = (const float*)d_in[0];   // [N, H]
    const float* W    = (const float*)d_in[1];   // [H, H]
    const float* attn = (const float*)d_in[2];   // [1, 2H]
    const int*   src  = (const int*)d_in[3];     // [E]
    const int*   dst  = (const int*)d_in[4];     // [E]
    float* out = (float*)d_out;                  // [N*H + 1]

    float *h_buf = nullptr, *cnt_ptr = nullptr;
    float *s0 = nullptr, *d0 = nullptr, *s1 = nullptr, *d1 = nullptr;
    cudaGetSymbolAddress((void**)&h_buf, g_h);
    cudaGetSymbolAddress((void**)&cnt_ptr, g_cnt);
    cudaGetSymbolAddress((void**)&s0, g_s0);
    cudaGetSymbolAddress((void**)&d0, g_d0);
    cudaGetSymbolAddress((void**)&s1, g_s1);
    cudaGetSymbolAddress((void**)&d1, g_d1);

    const int NB_NODE1  = (N_NODES + 255) / 256;       // 196
    const int NB_EQ     = (E_QUARTER + 255) / 256;     // 782
    const int NB_EDGE1  = (E_EDGES + 255) / 256;       // 3125
    const int NB_SCORE  = (N_NODES * 8 + 255) / 256;   // 1563
    const int NB_NODE16 = (N_NODES * 16) / 256;        // 3125 (exact)

    // Fork a side stream for the prep/scores branch. Host objects only
    // (no device memory). Created per call and intentionally NOT destroyed:
    // destroying a forked stream mid-capture invalidates the capture, and
    // kernel_launch only executes a handful of times (replays skip host code).
    cudaStream_t s2;
    cudaStreamCreateWithFlags(&s2, cudaStreamNonBlocking);
    cudaEvent_t evFork, evJoin;
    cudaEventCreateWithFlags(&evFork, cudaEventDisableTiming);
    cudaEventCreateWithFlags(&evJoin, cudaEventDisableTiming);

    cudaEventRecord(evFork, 0);
    cudaStreamWaitEvent(s2, evFork, 0);

    // ---- branch B (side stream): prep + layer-0 scores ----
    k_prep<<<1, 128, 0, s2>>>(W, attn);
    k_node_scores<<<NB_SCORE, 256, 0, s2>>>(emb);
    cudaEventRecord(evJoin, s2);

    // ---- branch A (capture stream): CSR build ----
    cudaMemsetAsync(cnt_ptr, 0, N_NODES * sizeof(unsigned));
    k_hist<<<NB_EQ, 256>>>(dst);
    k_scan1<<<SCAN_NBLK, SCAN_CHUNK>>>();
    k_scan23<<<NB_NODE1, 256>>>();
    k_scatter<<<NB_EDGE1, 256>>>(src, dst);

    // ---- join, then the fused layer/loss pipeline ----
    cudaStreamWaitEvent(0, evJoin, 0);
    k_layer<0, 1><<<NB_NODE16, 256>>>(emb, emb, h_buf, s0, d0);
    k_layer<1, 0><<<NB_NODE16, 256>>>(h_buf, emb, out, s1, d1);
    k_loss<<<NB_NODE16, 256>>>(out, out);
}

// round 14
// speedup vs baseline: 1.1163x; 1.1163x over previous
#include <cuda_runtime.h>
#include <cuda_bf16.h>
#include <cuda_fp16.h>

#define N_NODES 50000
#define E_EDGES 800000
#define H_DIM   64
#define GAMMA   0.2f

#define SCAN_CHUNK 1024
#define SCAN_NBLK  ((N_NODES + SCAN_CHUNK - 1) / SCAN_CHUNK)   // 49
#define E_QUARTER  (E_EDGES / 4)                               // 200000, exact

// ---------------- device scratch (static, allocation-free) ----------------
__device__ float    g_vsrc[H_DIM];
__device__ float    g_vdst[H_DIM];
__device__ float    g_s0[N_NODES];
__device__ float    g_d0[N_NODES];
__device__ float    g_s1[N_NODES];
__device__ float    g_d1[N_NODES];
__device__ unsigned g_cnt[N_NODES];
__device__ unsigned g_rowptr[N_NODES + 1];
__device__ unsigned g_cursor[N_NODES];
__device__ unsigned g_blksum[SCAN_NBLK];
__device__ int      g_srcs[E_EDGES];      // src id, grouped by dst (CSR)
__device__ float    g_ex[E_EDGES];        // last-layer exp(e), CSR order
__device__ float    g_dinv[N_NODES];      // last-layer 1/denom
__device__ __half   g_embh[N_NODES * H_DIM];  // fp16 copy of emb (gather operand)
__device__ __half   g_hh[N_NODES * H_DIM];    // fp16 h after layer0
__device__ __half   g_hh2[N_NODES * H_DIM];   // fp16 h after layer1 (loss gather)
__device__ float    g_sumA;
__device__ float    g_sumB;
__device__ unsigned g_done;

// 4 halfs -> float4
__device__ __forceinline__ float4 ld_half4(const __half* p) {
    uint2 r = *(const uint2*)p;
    float2 a = __half22float2(*(__half2*)&r.x);
    float2 b = __half22float2(*(__half2*)&r.y);
    return make_float4(a.x, a.y, b.x, b.y);
}
__device__ __forceinline__ void st_half4(__half* p, float4 v) {
    __half2 h0 = __floats2half2_rn(v.x, v.y);
    __half2 h1 = __floats2half2_rn(v.z, v.w);
    uint2 r;
    r.x = *(unsigned*)&h0;
    r.y = *(unsigned*)&h1;
    *(uint2*)p = r;
}

// ---------------- kernels ----------------

// fused: block 0 computes v_src/v_dst + zeros accumulators; all blocks
// histogram dst (x4 per thread: RED has no return -> safe to batch).
__global__ void k_prep_hist(const float* __restrict__ W, const float* __restrict__ attn,
                            const int* __restrict__ dst) {
    int i = blockIdx.x * blockDim.x + threadIdx.x;
    if (blockIdx.x == 0 && threadIdx.x < 128) {
        int t = threadIdx.x;
        if (t == 0) { g_sumA = 0.f; g_sumB = 0.f; g_done = 0u; }
        if (t < H_DIM) {
            float acc = 0.f;
            #pragma unroll 8
            for (int r = 0; r < H_DIM; r++) acc += attn[r] * W[r * H_DIM + t];
            g_vsrc[t] = acc;
        } else {
            int c = t - H_DIM;
            float acc = 0.f;
            #pragma unroll 8
            for (int r = 0; r < H_DIM; r++) acc += attn[H_DIM + r] * W[r * H_DIM + c];
            g_vdst[c] = acc;
        }
    }
    if (i < E_QUARTER) {
        int4 d = ((const int4*)dst)[i];
        atomicAdd(&g_cnt[d.x], 1u);
        atomicAdd(&g_cnt[d.y], 1u);
        atomicAdd(&g_cnt[d.z], 1u);
        atomicAdd(&g_cnt[d.w], 1u);
    }
}

// per-block exclusive scan of g_cnt -> g_rowptr (block-local), totals -> g_blksum
__global__ void k_scan1() {
    __shared__ unsigned warp_sums[32];
    int t = threadIdx.x, lane = t & 31, wid = t >> 5;
    int idx = blockIdx.x * SCAN_CHUNK + t;

    unsigned orig = (idx < N_NODES) ? g_cnt[idx] : 0u;
    unsigned v = orig;
    #pragma unroll
    for (int o = 1; o < 32; o <<= 1) {
        unsigned u = __shfl_up_sync(0xffffffffu, v, o);
        if (lane >= o) v += u;
    }
    if (lane == 31) warp_sums[wid] = v;
    __syncthreads();
    if (wid == 0) {
        unsigned w = warp_sums[lane];
        #pragma unroll
        for (int o = 1; o < 32; o <<= 1) {
            unsigned u = __shfl_up_sync(0xffffffffu, w, o);
            if (lane >= o) w += u;
        }
        warp_sums[lane] = w;
    }
    __syncthreads();
    unsigned pre = (wid > 0) ? warp_sums[wid - 1] : 0u;
    if (idx < N_NODES) g_rowptr[idx] = pre + v - orig;
    if (t == SCAN_CHUNK - 1) g_blksum[blockIdx.x] = warp_sums[31];
}

// fused scan2+3: each 256-thread block covers nodes inside ONE scan chunk.
__global__ void k_scan23() {
    __shared__ unsigned s_off;
    int chunk = (blockIdx.x * 256) / SCAN_CHUNK;

    if (threadIdx.x < 32) {
        unsigned v = 0;
        for (int k = threadIdx.x; k < chunk; k += 32) v += g_blksum[k];
        #pragma unroll
        for (int o = 16; o; o >>= 1) v += __shfl_xor_sync(0xffffffffu, v, o);
        if (threadIdx.x == 0) s_off = v;
    } else if (blockIdx.x == 0 && threadIdx.x < 64) {
        int lane = threadIdx.x - 32;
        unsigned v = 0;
        for (int k = lane; k < SCAN_NBLK; k += 32) v += g_blksum[k];
        #pragma unroll
        for (int o = 16; o; o >>= 1) v += __shfl_xor_sync(0xffffffffu, v, o);
        if (lane == 0) g_rowptr[N_NODES] = v;
    }
    __syncthreads();
    int i = blockIdx.x * 256 + threadIdx.x;
    if (i < N_NODES) {
        unsigned r = g_rowptr[i] + s_off;
        g_rowptr[i] = r;
        g_cursor[i] = r;
    }
}

// fused: scatter edges into CSR + layer-0 scores + fp16 emb copy.
__global__ void k_scatter_scores(const int* __restrict__ src, const int* __restrict__ dst,
                                 const float* __restrict__ emb) {
    int i = blockIdx.x * blockDim.x + threadIdx.x;
    if (i < E_EDGES) {
        unsigned pos = atomicAdd(&g_cursor[dst[i]], 1u);
        g_srcs[pos] = src[i];
    }
    if (i < N_NODES * 8) {
        int node = i >> 3;
        int part = i & 7;
        const float4* hp = (const float4*)(emb + (size_t)node * H_DIM);
        const float4* vs = (const float4*)g_vsrc;
        const float4* vd = (const float4*)g_vdst;
        float4 a = hp[part * 2], b = hp[part * 2 + 1];
        float4 v0 = vs[part * 2], v1 = vs[part * 2 + 1];
        float4 w0 = vd[part * 2], w1 = vd[part * 2 + 1];

        // fp16 copy of this 8-float slice (coalesced 16B per lane)
        __half* hcp = g_embh + (size_t)node * H_DIM + part * 8;
        st_half4(hcp, a);
        st_half4(hcp + 4, b);

        float s = a.x * v0.x + a.y * v0.y + a.z * v0.z + a.w * v0.w
                + b.x * v1.x + b.y * v1.y + b.z * v1.z + b.w * v1.w;
        float d = a.x * w0.x + a.y * w0.y + a.z * w0.z + a.w * w0.w
                + b.x * w1.x + b.y * w1.y + b.z * w1.z + b.w * w1.w;
        #pragma unroll
        for (int off = 4; off; off >>= 1) {
            s += __shfl_xor_sync(0xffffffffu, s, off);
            d += __shfl_xor_sync(0xffffffffu, d, off);
        }
        if (part == 0) { g_s0[node] = s; g_d0[node] = d; }
    }
}

// fused per-node layer, single pass; gathers fp16 rows, accumulates f32.
// FINAL: also write f32 out + fp16 copy, store ex/dinv, accumulate loss_a.
template <int FINAL, int WSCORES>
__global__ void k_layer(const __half* __restrict__ h_in,
                        const float* __restrict__ emb,
                        float* __restrict__ out_f32,
                        __half* __restrict__ h_out,
                        const float* __restrict__ s_in,
                        const float* __restrict__ d_in) {
    int gid  = blockIdx.x * blockDim.x + threadIdx.x;   // exact grid: N*16
    int node = gid >> 4;
    int part = gid & 15;

    unsigned beg = g_rowptr[node], end = g_rowptr[node + 1];
    float dloc = d_in[node];

    float4 acc = make_float4(0.f, 0.f, 0.f, 0.f);
    float den = 0.f;
    unsigned j = beg;
    for (; j + 4 <= end; j += 4) {
        int s0 = g_srcs[j], s1 = g_srcs[j + 1], s2 = g_srcs[j + 2], s3 = g_srcs[j + 3];
        float e0 = s_in[s0] + dloc, e1 = s_in[s1] + dloc,
              e2 = s_in[s2] + dloc, e3 = s_in[s3] + dloc;
        e0 = e0 > 0.f ? e0 : GAMMA * e0;  e1 = e1 > 0.f ? e1 : GAMMA * e1;
        e2 = e2 > 0.f ? e2 : GAMMA * e2;  e3 = e3 > 0.f ? e3 : GAMMA * e3;
        float x0 = __expf(e0), x1 = __expf(e1), x2 = __expf(e2), x3 = __expf(e3);
        float4 h0 = ld_half4(h_in + (size_t)s0 * H_DIM + part * 4);
        float4 h1 = ld_half4(h_in + (size_t)s1 * H_DIM + part * 4);
        float4 h2 = ld_half4(h_in + (size_t)s2 * H_DIM + part * 4);
        float4 h3 = ld_half4(h_in + (size_t)s3 * H_DIM + part * 4);
        den += (x0 + x1) + (x2 + x3);
        acc.x += x0 * h0.x + x1 * h1.x + x2 * h2.x + x3 * h3.x;
        acc.y += x0 * h0.y + x1 * h1.y + x2 * h2.y + x3 * h3.y;
        acc.z += x0 * h0.z + x1 * h1.z + x2 * h2.z + x3 * h3.z;
        acc.w += x0 * h0.w + x1 * h1.w + x2 * h2.w + x3 * h3.w;
        if (FINAL && part == 0) {
            g_ex[j] = x0; g_ex[j + 1] = x1; g_ex[j + 2] = x2; g_ex[j + 3] = x3;
        }
    }
    for (; j < end; j++) {
        int sj = g_srcs[j];
        float e = s_in[sj] + dloc;
        e = e > 0.f ? e : GAMMA * e;
        float ex = __expf(e);
        den += ex;
        float4 hv = ld_half4(h_in + (size_t)sj * H_DIM + part * 4);
        acc.x += ex * hv.x; acc.y += ex * hv.y;
        acc.z += ex * hv.z; acc.w += ex * hv.w;
        if (FINAL && part == 0) g_ex[j] = ex;
    }
    float inv = 1.f / fmaxf(den, 1e-16f);
    float4 eb = *(const float4*)(emb + (size_t)node * H_DIM + part * 4);
    float4 hv = make_float4(0.5f * (eb.x + acc.x * inv), 0.5f * (eb.y + acc.y * inv),
                            0.5f * (eb.z + acc.z * inv), 0.5f * (eb.w + acc.w * inv));
    st_half4(h_out + (size_t)node * H_DIM + part * 4, hv);
    if (FINAL)
        *(float4*)(out_f32 + (size_t)node * H_DIM + part * 4) = hv;

    // ----- post-loop: all 32 lanes reconverged; full-mask shuffles safe -----
    if (WSCORES) {
        float4 v0 = ((const float4*)g_vsrc)[part];
        float4 w0 = ((const float4*)g_vdst)[part];
        float sp = hv.x * v0.x + hv.y * v0.y + hv.z * v0.z + hv.w * v0.w;
        float dp = hv.x * w0.x + hv.y * w0.y + hv.z * w0.z + hv.w * w0.w;
        #pragma unroll
        for (int off = 8; off; off >>= 1) {
            sp += __shfl_xor_sync(0xffffffffu, sp, off);
            dp += __shfl_xor_sync(0xffffffffu, dp, off);
        }
        if (part == 0) { g_s1[node] = sp; g_d1[node] = dp; }
    }

    if (FINAL) {
        if (part == 0) g_dinv[node] = inv;
        float dx = hv.x - eb.x, dy = hv.y - eb.y, dz = hv.z - eb.z, dw = hv.w - eb.w;
        float sq = dx * dx + dy * dy + dz * dz + dw * dw;
        #pragma unroll
        for (int off = 16; off; off >>= 1) sq += __shfl_xor_sync(0xffffffffu, sq, off);
        __shared__ float sm[8];
        if ((threadIdx.x & 31) == 0) sm[threadIdx.x >> 5] = sq;
        __syncthreads();
        if (threadIdx.x < 8) {
            float v = sm[threadIdx.x];
            #pragma unroll
            for (int o = 4; o; o >>= 1) v += __shfl_xor_sync(0xffu, v, o);
            if (threadIdx.x == 0) atomicAdd(&g_sumA, v);
        }
    }
}

// loss_b on fp16 rows, lane-per-part (coalesced), unrolled x2; fused finalize.
__global__ void k_loss(const __half* __restrict__ h, float* __restrict__ out) {
    int gid  = blockIdx.x * blockDim.x + threadIdx.x;   // exact grid: N*16
    int node = gid >> 4;
    int part = gid & 15;
    unsigned gmask = 0xFFFFu << (threadIdx.x & 16);

    unsigned beg = g_rowptr[node], end = g_rowptr[node + 1];
    float4 hd = ld_half4(h + (size_t)node * H_DIM + part * 4);
    float dinv = g_dinv[node];

    float sum = 0.f;
    unsigned j = beg;
    for (; j + 2 <= end; j += 2) {
        int s0 = g_srcs[j], s1 = g_srcs[j + 1];
        float4 a0 = ld_half4(h + (size_t)s0 * H_DIM + part * 4);
        float4 a1 = ld_half4(h + (size_t)s1 * H_DIM + part * 4);
        float q0 = (hd.x - a0.x) * (hd.x - a0.x) + (hd.y - a0.y) * (hd.y - a0.y)
                 + (hd.z - a0.z) * (hd.z - a0.z) + (hd.w - a0.w) * (hd.w - a0.w);
        float q1 = (hd.x - a1.x) * (hd.x - a1.x) + (hd.y - a1.y) * (hd.y - a1.y)
                 + (hd.z - a1.z) * (hd.z - a1.z) + (hd.w - a1.w) * (hd.w - a1.w);
        #pragma unroll
        for (int off = 8; off; off >>= 1) {
            q0 += __shfl_xor_sync(gmask, q0, off);
            q1 += __shfl_xor_sync(gmask, q1, off);
        }
        sum += g_ex[j] * sqrtf(q0 + 1e-12f) + g_ex[j + 1] * sqrtf(q1 + 1e-12f);
    }
    if (j < end) {
        int sj = g_srcs[j];
        float4 a = ld_half4(h + (size_t)sj * H_DIM + part * 4);
        float q = (hd.x - a.x) * (hd.x - a.x) + (hd.y - a.y) * (hd.y - a.y)
                + (hd.z - a.z) * (hd.z - a.z) + (hd.w - a.w) * (hd.w - a.w);
        #pragma unroll
        for (int off = 8; off; off >>= 1) q += __shfl_xor_sync(gmask, q, off);
        sum += g_ex[j] * sqrtf(q + 1e-12f);
    }
    sum = (part == 0) ? sum * dinv : 0.f;
    #pragma unroll
    for (int off = 16; off; off >>= 1) sum += __shfl_xor_sync(0xffffffffu, sum, off);
    __shared__ float sm[8];
    if ((threadIdx.x & 31) == 0) sm[threadIdx.x >> 5] = sum;
    __syncthreads();
    if (threadIdx.x < 8) {
        float v = sm[threadIdx.x];
        #pragma unroll
        for (int o = 4; o; o >>= 1) v += __shfl_xor_sync(0xffu, v, o);
        if (threadIdx.x == 0) {
            atomicAdd(&g_sumB, v);
            __threadfence();
            unsigned ticket = atomicAdd(&g_done, 1u);
            if (ticket == gridDim.x - 1) {
                float a = *(volatile float*)&g_sumA;
                float b = *(volatile float*)&g_sumB;
                out[N_NODES * H_DIM] = 0.5f * (a + b) / (float)N_NODES;
            }
        }
    }
}

// ---------------- launch ----------------
extern "C" void kernel_launch(void* const* d_in, const int* in_sizes, int n_in,
                              void* d_out, int out_size) {
    const float* emb  = (const float*)d_in[0];   // [N, H]
    const float* W    = (const float*)d_in[1];   // [H, H]
    const float* attn = (const float*)d_in[2];   // [1, 2H]
    const int*   src  = (const int*)d_in[3];     // [E]
    const int*   dst  = (const int*)d_in[4];     // [E]
    float* out = (float*)d_out;                  // [N*H + 1]

    float *cnt_ptr = nullptr;
    float *s0 = nullptr, *d0 = nullptr, *s1 = nullptr, *d1 = nullptr;
    __half *embh = nullptr, *hh = nullptr, *hh2 = nullptr;
    cudaGetSymbolAddress((void**)&cnt_ptr, g_cnt);
    cudaGetSymbolAddress((void**)&s0, g_s0);
    cudaGetSymbolAddress((void**)&d0, g_d0);
    cudaGetSymbolAddress((void**)&s1, g_s1);
    cudaGetSymbolAddress((void**)&d1, g_d1);
    cudaGetSymbolAddress((void**)&embh, g_embh);
    cudaGetSymbolAddress((void**)&hh, g_hh);
    cudaGetSymbolAddress((void**)&hh2, g_hh2);

    const int NB_NODE1  = (N_NODES + 255) / 256;       // 196
    const int NB_EQ     = (E_QUARTER + 255) / 256;     // 782
    const int NB_EDGE1  = (E_EDGES + 255) / 256;       // 3125
    const int NB_NODE16 = (N_NODES * 16) / 256;        // 3125 (exact)

    // ---- CSR build + prep, fused/hierarchical (serial: fork measured slower) ----
    cudaMemsetAsync(cnt_ptr, 0, N_NODES * sizeof(unsigned));
    k_prep_hist<<<NB_EQ, 256>>>(W, attn, dst);
    k_scan1<<<SCAN_NBLK, SCAN_CHUNK>>>();
    k_scan23<<<NB_NODE1, 256>>>();
    k_scatter_scores<<<NB_EDGE1, 256>>>(src, dst, emb);

    // ---- layer 0 (embh -> hh fp16), fused next-layer scores ----
    k_layer<0, 1><<<NB_NODE16, 256>>>(embh, emb, out, hh, s0, d0);

    // ---- layer 1 (hh -> out f32 + hh2 fp16), final ----
    k_layer<1, 0><<<NB_NODE16, 256>>>(hh, emb, out, hh2, s1, d1);

    // ---- loss_b on fp16 rows + fused finalize ----
    k_loss<<<NB_NODE16, 256>>>(hh2, out);
}